// round 10
// baseline (speedup 1.0000x reference)
#include <cuda_runtime.h>
#include <math.h>

#define NB 4
#define NV 4096
#define NT 8192
#define NP 4096
#define EPSF 1e-12f
#define BIGF 3.402823466e38f

#define TPB 128
#define PPT 4              // points per thread (2 packed f32x2 streams)
#define TILE 128           // triangles staged in smem per tile
#define CHUNKS 32
#define CHUNK_TRIS (NT / CHUNKS)      // 256
#define PH_CHUNKS 16
#define PH_CHUNK (NT / PH_CHUNKS)     // 512
#define PGROUP (PPT * TPB)            // 512 points per block
#define F4_PER_TRI 11

typedef unsigned long long ull;

static __device__ float g_pos[NB * NV * 3];
static __device__ float4 g_tri2[NB * NT * F4_PER_TRI];
static __device__ float4 g_triz[NB * NT];       // (nx,ny,nz,Kn) compact
static __device__ float4 g_centd[NB * NT * 2];  // dup negated centroid
static __device__ unsigned int g_dmin[NB * NP];
static __device__ float g_spts[NB * NP * 3];    // spatially sorted points
static __device__ int g_cellid[NB * NP];
static __device__ int g_hist[NB * 512];
static __device__ int g_scan[NB * 512];
static __device__ float g_psum[32];
static __device__ float g_pcnt[32];

// ---------- packed f32x2 helpers ----------
__device__ __forceinline__ ull f2x(float lo, float hi) {
    ull r; asm("mov.b64 %0, {%1, %2};" : "=l"(r) : "f"(lo), "f"(hi)); return r;
}
__device__ __forceinline__ ull f2x_add(ull a, ull b) {
    ull r; asm("add.rn.f32x2 %0, %1, %2;" : "=l"(r) : "l"(a), "l"(b)); return r;
}
__device__ __forceinline__ ull f2x_mul(ull a, ull b) {
    ull r; asm("mul.rn.f32x2 %0, %1, %2;" : "=l"(r) : "l"(a), "l"(b)); return r;
}
__device__ __forceinline__ ull f2x_fma(ull a, ull b, ull c) {
    ull r; asm("fma.rn.f32x2 %0, %1, %2, %3;" : "=l"(r) : "l"(a), "l"(b), "l"(c)); return r;
}
__device__ __forceinline__ float f2lo(ull v) { return __uint_as_float((unsigned)v); }
__device__ __forceinline__ float f2hi(ull v) { return __uint_as_float((unsigned)(v >> 32)); }

__device__ __forceinline__ float safe_inv(float x) {
    return (fabsf(x) < EPSF) ? 1.0f : (1.0f / x);
}

// Kernel 1: sigmoid + transpose.
__global__ void prep_kernel(const float* __restrict__ vertices) {
    int idx = blockIdx.x * blockDim.x + threadIdx.x;
    if (idx < NB * 3 * NV) {
        int b = idx / (3 * NV);
        int r = idx - b * 3 * NV;
        int d = r / NV;
        int w = r - d * NV;
        float v = vertices[idx];
        g_pos[(b * NV + w) * 3 + d] = 1.0f / (1.0f + expf(-v));
    }
}

// Kernel 2: per-triangle frame + 2D constants + plane consts + centroid.
__global__ void tri_kernel(const int* __restrict__ faces) {
    int idx = blockIdx.x * blockDim.x + threadIdx.x;
    if (idx >= NB * NT) return;
    int b = idx >> 13;
    int t = idx & (NT - 1);
    int i0 = faces[t * 3 + 0], i1 = faces[t * 3 + 1], i2 = faces[t * 3 + 2];
    const float* base = g_pos + b * NV * 3;
    float ax = base[i0 * 3 + 0], ay = base[i0 * 3 + 1], az = base[i0 * 3 + 2];
    float bxp = base[i1 * 3 + 0], byp = base[i1 * 3 + 1], bzp = base[i1 * 3 + 2];
    float cxp = base[i2 * 3 + 0], cyp = base[i2 * 3 + 1], czp = base[i2 * 3 + 2];
    float e1x = bxp - ax, e1y = byp - ay, e1z = bzp - az;
    float acx = cxp - ax, acy = cyp - ay, acz = czp - az;
    float l1 = e1x * e1x + e1y * e1y + e1z * e1z;
    float ux, uy, uz;
    if (l1 < EPSF) { ux = 1.0f; uy = 0.0f; uz = 0.0f; }
    else {
        float inv = 1.0f / sqrtf(l1);
        ux = e1x * inv; uy = e1y * inv; uz = e1z * inv;
    }
    float du = acx * ux + acy * uy + acz * uz;
    float wx = acx - du * ux, wy = acy - du * uy, wz = acz - du * uz;
    float l2 = wx * wx + wy * wy + wz * wz;
    float vx, vy, vz;
    if (l2 < EPSF) {
        float tx = uy, ty = -ux, tz = 0.0f;
        float lt = tx * tx + ty * ty;
        if (lt < 1e-8f) { tx = -uz; ty = 0.0f; tz = ux; lt = tx * tx + tz * tz; }
        float inv = 1.0f / sqrtf(lt);
        vx = tx * inv; vy = ty * inv; vz = tz * inv;
    } else {
        float inv = 1.0f / sqrtf(l2);
        vx = wx * inv; vy = wy * inv; vz = wz * inv;
    }
    float nx = uy * vz - uz * vy;
    float ny = uz * vx - ux * vz;
    float nz = ux * vy - uy * vx;
    float Ku = -(ax * ux + ay * uy + az * uz);
    float Kv = -(ax * vx + ay * vy + az * vz);
    float Kn = -(ax * nx + ay * ny + az * nz);
    float bx = e1x * ux + e1y * uy + e1z * uz;
    float cx = acx * ux + acy * uy + acz * uz;
    float cy = acx * vx + acy * vy + acz * vz;
    float dx = cx - bx;
    float ac2 = cx * cx + cy * cy;
    float bc2 = dx * dx + cy * cy;
    float4* o = g_tri2 + (size_t)idx * F4_PER_TRI;
    o[0]  = make_float4(ux, ux, uy, uy);
    o[1]  = make_float4(uz, uz, Ku, Ku);
    o[2]  = make_float4(vx, vx, vy, vy);
    o[3]  = make_float4(vz, vz, Kv, Kv);
    o[4]  = make_float4(nx, nx, ny, ny);
    o[5]  = make_float4(nz, nz, Kn, Kn);
    o[6]  = make_float4(-bx, -bx, cx, cx);
    o[7]  = make_float4(cy, cy, -cx, -cx);
    o[8]  = make_float4(-cy, -cy, dx, dx);
    o[9]  = make_float4(-safe_inv(ac2), -safe_inv(ac2), -ac2, -ac2);
    o[10] = make_float4(-safe_inv(bc2), -safe_inv(bc2), -bc2, -bc2);
    g_triz[idx] = make_float4(nx, ny, nz, Kn);
    float gx = (ax + bxp + cxp) * (1.0f / 3.0f);
    float gy = (ay + byp + cyp) * (1.0f / 3.0f);
    float gz = (az + bzp + czp) * (1.0f / 3.0f);
    g_centd[idx * 2 + 0] = make_float4(-gx, -gx, -gy, -gy);
    g_centd[idx * 2 + 1] = make_float4(-gz, -gz, 0.0f, 0.0f);
}

// Kernel 3a: zero hist + init dmin.
__global__ void zero_kernel() {
    int idx = blockIdx.x * blockDim.x + threadIdx.x;
    if (idx < NB * NP) g_dmin[idx] = 0x7F7FFFFFu;
    if (idx < NB * 512) g_hist[idx] = 0;
}

__device__ __forceinline__ int spread3(int v) {
    return (v & 1) | ((v & 2) << 2) | ((v & 4) << 4);
}

// Kernel 3b: morton cell id + histogram.
__global__ void cellid_kernel(const float* __restrict__ pc) {
    int idx = blockIdx.x * blockDim.x + threadIdx.x;
    if (idx >= NB * NP) return;
    float x = pc[idx * 3 + 0], y = pc[idx * 3 + 1], z = pc[idx * 3 + 2];
    int cx = min(7, max(0, (int)(x * 8.0f)));
    int cy = min(7, max(0, (int)(y * 8.0f)));
    int cz = min(7, max(0, (int)(z * 8.0f)));
    int cell = spread3(cx) | (spread3(cy) << 1) | (spread3(cz) << 2);
    g_cellid[idx] = cell;
    int b = idx >> 12;
    atomicAdd(&g_hist[b * 512 + cell], 1);
}

// Kernel 3c: per-batch exclusive scan of 512-bin histograms (1 block).
__global__ void scan_kernel() {
    __shared__ int s[512];
    int t = threadIdx.x;
    for (int b = 0; b < NB; b++) {
        int h = g_hist[b * 512 + t];
        s[t] = h;
        __syncthreads();
        for (int o = 1; o < 512; o <<= 1) {
            int v = (t >= o) ? s[t - o] : 0;
            __syncthreads();
            s[t] += v;
            __syncthreads();
        }
        g_scan[b * 512 + t] = s[t] - h;   // exclusive
        __syncthreads();
    }
}

// Kernel 3d: deterministic per-cell scatter (index order preserved in cell).
__global__ void scatter_kernel(const float* __restrict__ pc) {
    int b = blockIdx.x;
    int cell = threadIdx.x;
    int off = g_scan[b * 512 + cell];
    const int4* ids4 = (const int4*)(g_cellid + b * NP);
    const float* src = pc + (size_t)b * NP * 3;
    float* dst = g_spts + (size_t)b * NP * 3;
    for (int q = 0; q < NP / 4; q++) {
        int4 v = ids4[q];
        int i = q * 4;
        if (v.x == cell) { dst[off*3] = src[i*3]; dst[off*3+1] = src[i*3+1]; dst[off*3+2] = src[i*3+2]; off++; }
        if (v.y == cell) { dst[off*3] = src[(i+1)*3]; dst[off*3+1] = src[(i+1)*3+1]; dst[off*3+2] = src[(i+1)*3+2]; off++; }
        if (v.z == cell) { dst[off*3] = src[(i+2)*3]; dst[off*3+1] = src[(i+2)*3+1]; dst[off*3+2] = src[(i+2)*3+2]; off++; }
        if (v.w == cell) { dst[off*3] = src[(i+3)*3]; dst[off*3+1] = src[(i+3)*3+1]; dst[off*3+2] = src[(i+3)*3+2]; off++; }
    }
}

// Kernel 4: Phase A — upper bound = min dist^2 to all centroids.
__global__ void __launch_bounds__(TPB) phaseA_kernel() {
    __shared__ float4 sC[TILE * 2];
    int b = blockIdx.z;
    int tid = threadIdx.x;
    int warp = tid >> 5, lane = tid & 31;
    int ibase = blockIdx.y * PGROUP + warp * 128 + lane;
    const float* S = g_spts + (size_t)b * NP * 3;
    float px[PPT], py[PPT], pz[PPT], um[PPT];
#pragma unroll
    for (int k = 0; k < PPT; k++) {
        int i = ibase + 32 * k;
        px[k] = S[i * 3 + 0]; py[k] = S[i * 3 + 1]; pz[k] = S[i * 3 + 2];
        um[k] = BIGF;
    }
    ull px2[2], py2[2], pz2[2];
#pragma unroll
    for (int j = 0; j < 2; j++) {
        px2[j] = f2x(px[2*j], px[2*j+1]);
        py2[j] = f2x(py[2*j], py[2*j+1]);
        pz2[j] = f2x(pz[2*j], pz[2*j+1]);
    }
    const float4* base = g_centd + ((size_t)b * NT + (size_t)blockIdx.x * PH_CHUNK) * 2;
    for (int tt = 0; tt < PH_CHUNK / TILE; tt++) {
        __syncthreads();
        const float4* src = base + (size_t)tt * TILE * 2;
#pragma unroll
        for (int i = 0; i < 2; i++)
            sC[tid + i * TPB] = src[tid + i * TPB];
        __syncthreads();
#pragma unroll 4
        for (int t = 0; t < TILE; t++) {
            const ulonglong2* cp = (const ulonglong2*)(sC + t * 2);
            ulonglong2 c0 = cp[0], c1 = cp[1];
#pragma unroll
            for (int j = 0; j < 2; j++) {
                ull dx = f2x_add(px2[j], c0.x);
                ull dy = f2x_add(py2[j], c0.y);
                ull dz = f2x_add(pz2[j], c1.x);
                ull d = f2x_fma(dx, dx, f2x_fma(dy, dy, f2x_mul(dz, dz)));
                um[2*j]   = fminf(um[2*j],   f2lo(d));
                um[2*j+1] = fminf(um[2*j+1], f2hi(d));
            }
        }
    }
#pragma unroll
    for (int k = 0; k < PPT; k++)
        atomicMin(&g_dmin[b * NP + ibase + 32 * k], __float_as_uint(um[k]));
}

// Min-of-features full eval (converged R6 structure).
__device__ __forceinline__ void tri_pair(const ulonglong2* __restrict__ tp,
                                         ull px, ull py, ull pz,
                                         float& m0, float& m1)
{
    ulonglong2 c0 = tp[0], c1 = tp[1], c2 = tp[2], c3 = tp[3], c4 = tp[4], c5 = tp[5];
    ull x = f2x_fma(c0.x, px, f2x_fma(c0.y, py, f2x_fma(c1.x, pz, c1.y)));
    ull y = f2x_fma(c2.x, px, f2x_fma(c2.y, py, f2x_fma(c3.x, pz, c3.y)));
    ull z = f2x_fma(c4.x, px, f2x_fma(c4.y, py, f2x_fma(c5.x, pz, c5.y)));
    ulonglong2 c6 = tp[6], c7 = tp[7], c8 = tp[8], c9 = tp[9], c10 = tp[10];
    ull z2  = f2x_mul(z, z);
    ull zy2 = f2x_fma(y, y, z2);
    ull pa2 = f2x_fma(x, x, zy2);
    ull xb  = f2x_add(x, c6.x);
    ull pb2 = f2x_fma(xb, xb, zy2);
    ull xc  = f2x_add(x, c7.y);
    ull yc  = f2x_add(y, c8.x);
    ull pc2 = f2x_fma(xc, xc, f2x_fma(yc, yc, z2));
    ull d2  = f2x_fma(y, c7.x, f2x_mul(x, c6.y));
    ull dAC = f2x_fma(f2x_mul(d2, d2), c9.x, pa2);
    ull gac = f2x_add(d2, c9.y);
    ull e   = f2x_fma(y, c7.x, f2x_mul(xb, c8.y));
    ull dBC = f2x_fma(f2x_mul(e, e), c10.x, pb2);
    ull gbc = f2x_add(e, c10.y);
    ull u0  = f2x_fma(x, c7.x, f2x_mul(y, c7.y));
    ull w2  = f2x_fma(y, c8.y, f2x_mul(xb, c8.x));
    {
        float m = fminf(fminf(f2lo(pa2), f2lo(pb2)), f2lo(pc2));
        if (f2lo(x) > 0.0f && f2lo(xb) < 0.0f) m = fminf(m, f2lo(zy2));
        if (f2lo(d2) > 0.0f && f2lo(gac) < 0.0f) m = fminf(m, f2lo(dAC));
        if (f2lo(e) > 0.0f && f2lo(gbc) < 0.0f) m = fminf(m, f2lo(dBC));
        if (f2lo(y) > 0.0f && f2lo(u0) > 0.0f && f2lo(w2) > 0.0f) m = fminf(m, f2lo(z2));
        m0 = fminf(m0, m);
    }
    {
        float m = fminf(fminf(f2hi(pa2), f2hi(pb2)), f2hi(pc2));
        if (f2hi(x) > 0.0f && f2hi(xb) < 0.0f) m = fminf(m, f2hi(zy2));
        if (f2hi(d2) > 0.0f && f2hi(gac) < 0.0f) m = fminf(m, f2hi(dAC));
        if (f2hi(e) > 0.0f && f2hi(gbc) < 0.0f) m = fminf(m, f2hi(dBC));
        if (f2hi(y) > 0.0f && f2hi(u0) > 0.0f && f2hi(w2) > 0.0f) m = fminf(m, f2hi(z2));
        m1 = fminf(m1, m);
    }
}

// Kernel 5: culled brute force. Warp = 128 contiguous sorted points.
// Per 32 triangles: each lane cheap-tests one triangle's plane against the
// warp bounding sphere + current-best bound; survivors broadcast-evaluated.
__global__ void __launch_bounds__(TPB, 5) dist_kernel() {
    __shared__ float4 sT[TILE * F4_PER_TRI];
    __shared__ float4 sZ[TILE];
    int b = blockIdx.z;
    int tid = threadIdx.x;
    int warp = tid >> 5, lane = tid & 31;
    int ibase = blockIdx.y * PGROUP + warp * 128 + lane;
    const float* S = g_spts + (size_t)b * NP * 3;

    float px[PPT], py[PPT], pz[PPT], dm[PPT];
#pragma unroll
    for (int k = 0; k < PPT; k++) {
        int i = ibase + 32 * k;
        px[k] = S[i * 3 + 0]; py[k] = S[i * 3 + 1]; pz[k] = S[i * 3 + 2];
        dm[k] = __uint_as_float(g_dmin[b * NP + i]);   // Phase A seed
    }
    ull px2[2], py2[2], pz2[2];
#pragma unroll
    for (int j = 0; j < 2; j++) {
        px2[j] = f2x(px[2*j], px[2*j+1]);
        py2[j] = f2x(py[2*j], py[2*j+1]);
        pz2[j] = f2x(pz[2*j], pz[2*j+1]);
    }
    // warp bounding sphere over its 128 points
    float mnx = fminf(fminf(px[0], px[1]), fminf(px[2], px[3]));
    float mxx = fmaxf(fmaxf(px[0], px[1]), fmaxf(px[2], px[3]));
    float mny = fminf(fminf(py[0], py[1]), fminf(py[2], py[3]));
    float mxy = fmaxf(fmaxf(py[0], py[1]), fmaxf(py[2], py[3]));
    float mnz = fminf(fminf(pz[0], pz[1]), fminf(pz[2], pz[3]));
    float mxz = fmaxf(fmaxf(pz[0], pz[1]), fmaxf(pz[2], pz[3]));
#pragma unroll
    for (int o = 16; o > 0; o >>= 1) {
        mnx = fminf(mnx, __shfl_xor_sync(0xFFFFFFFFu, mnx, o));
        mxx = fmaxf(mxx, __shfl_xor_sync(0xFFFFFFFFu, mxx, o));
        mny = fminf(mny, __shfl_xor_sync(0xFFFFFFFFu, mny, o));
        mxy = fmaxf(mxy, __shfl_xor_sync(0xFFFFFFFFu, mxy, o));
        mnz = fminf(mnz, __shfl_xor_sync(0xFFFFFFFFu, mnz, o));
        mxz = fmaxf(mxz, __shfl_xor_sync(0xFFFFFFFFu, mxz, o));
    }
    float Wx = 0.5f * (mnx + mxx), Wy = 0.5f * (mny + mxy), Wz = 0.5f * (mnz + mxz);
    float ex = mxx - mnx, ey = mxy - mny, ez = mxz - mnz;
    float rw = 0.5f * sqrtf(ex * ex + ey * ey + ez * ez);

    const float4* triBase = g_tri2 + ((size_t)b * NT + (size_t)blockIdx.x * CHUNK_TRIS) * F4_PER_TRI;
    const float4* zBase   = g_triz + ((size_t)b * NT + (size_t)blockIdx.x * CHUNK_TRIS);

    for (int tt = 0; tt < CHUNK_TRIS / TILE; tt++) {
        __syncthreads();
        const float4* src = triBase + (size_t)tt * TILE * F4_PER_TRI;
#pragma unroll
        for (int i = 0; i < F4_PER_TRI; i++)
            sT[tid + i * TPB] = src[tid + i * TPB];
        sZ[tid] = zBase[tt * TILE + tid];
        __syncthreads();
        // refresh conservative threshold once per tile
        float dmax = fmaxf(fmaxf(dm[0], dm[1]), fmaxf(dm[2], dm[3]));
#pragma unroll
        for (int o = 16; o > 0; o >>= 1)
            dmax = fmaxf(dmax, __shfl_xor_sync(0xFFFFFFFFu, dmax, o));
        float thr = rw + sqrtf(dmax);
        thr *= thr;
#pragma unroll
        for (int sub = 0; sub < TILE / 32; sub++) {
            float4 zc = sZ[sub * 32 + lane];
            float zW = fmaf(zc.x, Wx, fmaf(zc.y, Wy, fmaf(zc.z, Wz, zc.w)));
            unsigned mask = __ballot_sync(0xFFFFFFFFu, zW * zW < thr);
            while (mask) {
                int j = __ffs(mask) - 1;
                mask &= mask - 1;
                const ulonglong2* tp = (const ulonglong2*)(sT + (sub * 32 + j) * F4_PER_TRI);
                tri_pair(tp, px2[0], py2[0], pz2[0], dm[0], dm[1]);
                tri_pair(tp, px2[1], py2[1], pz2[1], dm[2], dm[3]);
            }
        }
    }
#pragma unroll
    for (int k = 0; k < PPT; k++)
        atomicMin(&g_dmin[b * NP + ibase + 32 * k], __float_as_uint(dm[k]));
}

// Kernel 6a: parallel partial reduce over sorted points (order-invariant sum).
__global__ void reduceA_kernel() {
    __shared__ float sd[512];
    __shared__ float sc[512];
    int tid = threadIdx.x;
    int blk = blockIdx.x;
    int b = blk >> 3;
    int slice = blk & 7;
    int i = slice * 512 + tid;
    const float* p = g_spts + ((size_t)b * NP + i) * 3;
    float x = p[0], y = p[1], z = p[2];
    float m = (x != 0.0f || y != 0.0f || z != 0.0f) ? 1.0f : 0.0f;
    sd[tid] = __uint_as_float(g_dmin[b * NP + i]) * m;
    sc[tid] = m;
    __syncthreads();
    for (int s = 256; s > 0; s >>= 1) {
        if (tid < s) {
            sd[tid] += sd[tid + s];
            sc[tid] += sc[tid + s];
        }
        __syncthreads();
    }
    if (tid == 0) {
        g_psum[blk] = sd[0];
        g_pcnt[blk] = sc[0];
    }
}

// Kernel 6b: deterministic final combine.
__global__ void reduceB_kernel(float* __restrict__ out) {
    if (threadIdx.x == 0) {
        float acc = 0.0f;
        for (int b = 0; b < NB; b++) {
            float s = 0.0f, c = 0.0f;
#pragma unroll
            for (int j = 0; j < 8; j++) {
                s += g_psum[b * 8 + j];
                c += g_pcnt[b * 8 + j];
            }
            acc += s / fmaxf(c, 1.0f);
        }
        out[0] = acc * (1.0f / NB);
    }
}

extern "C" void kernel_launch(void* const* d_in, const int* in_sizes, int n_in,
                              void* d_out, int out_size) {
    const float* vertices = (const float*)d_in[0];
    const float* pc = (const float*)d_in[1];
    const int* faces = (const int*)d_in[2];
    float* out = (float*)d_out;

    prep_kernel<<<(NB * 3 * NV + 255) / 256, 256>>>(vertices);
    tri_kernel<<<(NB * NT + 255) / 256, 256>>>(faces);
    zero_kernel<<<(NB * NP + 255) / 256, 256>>>();
    cellid_kernel<<<(NB * NP + 255) / 256, 256>>>(pc);
    scan_kernel<<<1, 512>>>();
    scatter_kernel<<<NB, 512>>>(pc);
    phaseA_kernel<<<dim3(PH_CHUNKS, NP / PGROUP, NB), TPB>>>();
    dist_kernel<<<dim3(CHUNKS, NP / PGROUP, NB), TPB>>>();
    reduceA_kernel<<<32, 512>>>();
    reduceB_kernel<<<1, 32>>>(out);
}

// round 12
// speedup vs baseline: 2.4409x; 2.4409x over previous
#include <cuda_runtime.h>

#define NB 4
#define NV 4096
#define NT 8192
#define NP 4096
#define EPSF 1e-12f
#define BIGF 3.402823466e38f

#define TPB 128
#define PPT 4              // points per thread (2 packed f32x2 streams)
#define TILE 128           // triangles staged in smem per tile
#define CHUNKS 64          // grid 2048 blocks: kill 2-wave quantization tail
#define CHUNK_TRIS (NT / CHUNKS)   // 128 == TILE
#define F4_PER_TRI 9       // 144 bytes per triangle, constants pre-duplicated

typedef unsigned long long ull;

static __device__ float g_pos[NB * NV * 3];
static __device__ float4 g_tri2[NB * NT * F4_PER_TRI];
static __device__ unsigned int g_dmin[NB * NP];
static __device__ float g_psum[32];
static __device__ float g_pcnt[32];

// ---------- packed f32x2 helpers (SASS FADD2/FMUL2/FFMA2) ----------
__device__ __forceinline__ ull f2x(float lo, float hi) {
    ull r; asm("mov.b64 %0, {%1, %2};" : "=l"(r) : "f"(lo), "f"(hi)); return r;
}
__device__ __forceinline__ ull f2x_add(ull a, ull b) {
    ull r; asm("add.rn.f32x2 %0, %1, %2;" : "=l"(r) : "l"(a), "l"(b)); return r;
}
__device__ __forceinline__ ull f2x_mul(ull a, ull b) {
    ull r; asm("mul.rn.f32x2 %0, %1, %2;" : "=l"(r) : "l"(a), "l"(b)); return r;
}
__device__ __forceinline__ ull f2x_fma(ull a, ull b, ull c) {
    ull r; asm("fma.rn.f32x2 %0, %1, %2, %3;" : "=l"(r) : "l"(a), "l"(b), "l"(c)); return r;
}
__device__ __forceinline__ float f2lo(ull v) { return __uint_as_float((unsigned)v); }
__device__ __forceinline__ float f2hi(ull v) { return __uint_as_float((unsigned)(v >> 32)); }

__device__ __forceinline__ float safe_inv(float x) {
    return (fabsf(x) < EPSF) ? 1.0f : (1.0f / x);
}

// Kernel 1: sigmoid + layout transpose (B,3,4096)->(B,4096,3), and init dmin.
__global__ void prep_kernel(const float* __restrict__ vertices) {
    int idx = blockIdx.x * blockDim.x + threadIdx.x;
    if (idx < NB * 3 * NV) {
        int b = idx / (3 * NV);
        int r = idx - b * 3 * NV;
        int d = r / NV;
        int w = r - d * NV;
        float v = vertices[idx];
        float s = 1.0f / (1.0f + expf(-v));
        g_pos[(b * NV + w) * 3 + d] = s;
    }
    if (idx < NB * NP) g_dmin[idx] = 0x7F7FFFFFu;  // +FLT_MAX bits
}

// Kernel 2: per-triangle precompute, constants duplicated into f32x2 pairs.
// Pair map: c0:(-ax,-ay) c1:(-az,abx) c2:(aby,abz) c3:(acx,acy) c4:(acz,-ab2)
//           c5:(-abac,-ac2) c6:(-iab2,-iac2) c7:(-ibc2,den) c8:(-iden,0)
__global__ void tri_kernel(const int* __restrict__ faces) {
    int idx = blockIdx.x * blockDim.x + threadIdx.x;
    if (idx >= NB * NT) return;
    int b = idx >> 13;
    int t = idx & (NT - 1);
    int i0 = faces[t * 3 + 0], i1 = faces[t * 3 + 1], i2 = faces[t * 3 + 2];
    const float* base = g_pos + b * NV * 3;
    float ax = base[i0 * 3 + 0], ay = base[i0 * 3 + 1], az = base[i0 * 3 + 2];
    float bx = base[i1 * 3 + 0], by = base[i1 * 3 + 1], bz = base[i1 * 3 + 2];
    float cx = base[i2 * 3 + 0], cy = base[i2 * 3 + 1], cz = base[i2 * 3 + 2];
    float abx = bx - ax, aby = by - ay, abz = bz - az;
    float acx = cx - ax, acy = cy - ay, acz = cz - az;
    float bcx = cx - bx, bcy = cy - by, bcz = cz - bz;
    float ab2  = abx * abx + aby * aby + abz * abz;
    float ac2  = acx * acx + acy * acy + acz * acz;
    float abac = abx * acx + aby * acy + abz * acz;
    float bc2  = bcx * bcx + bcy * bcy + bcz * bcz;
    float den  = ab2 * ac2 - abac * abac;   // == va+vb+vc
    float4* o = g_tri2 + (size_t)idx * F4_PER_TRI;
    o[0] = make_float4(-ax, -ax, -ay, -ay);
    o[1] = make_float4(-az, -az, abx, abx);
    o[2] = make_float4(aby, aby, abz, abz);
    o[3] = make_float4(acx, acx, acy, acy);
    o[4] = make_float4(acz, acz, -ab2, -ab2);
    o[5] = make_float4(-abac, -abac, -ac2, -ac2);
    o[6] = make_float4(-safe_inv(ab2), -safe_inv(ab2), -safe_inv(ac2), -safe_inv(ac2));
    o[7] = make_float4(-safe_inv(bc2), -safe_inv(bc2), den, den);
    o[8] = make_float4(-safe_inv(den), -safe_inv(den), 0.0f, 0.0f);
}

// Min-of-features closest distance, one triangle vs two packed points.
// m = min(pa2, pb2, pc2,
//         lineAB if 0<d1<ab2, lineAC if 0<d2<ac2 (d6<0), lineBC if e>0 && f>0,
//         face   if va,vb,vc > 0)
// Line dists: pa2 - d1^2/ab2 etc. Face: pa2 - (vb*d1 + vc*d2)/den (normal eqs).
__device__ __forceinline__ void tri_pair(const ulonglong2* __restrict__ tp,
                                         ull px, ull py, ull pz, ull NEG1,
                                         float& m0, float& m1)
{
    ulonglong2 c0 = tp[0], c1 = tp[1], c2 = tp[2], c3 = tp[3], c4 = tp[4];
    ull apx = f2x_add(px, c0.x);
    ull apy = f2x_add(py, c0.y);
    ull apz = f2x_add(pz, c1.x);
    ull pa2 = f2x_fma(apx, apx, f2x_fma(apy, apy, f2x_mul(apz, apz)));
    ull d1  = f2x_fma(c1.y, apx, f2x_fma(c2.x, apy, f2x_mul(c2.y, apz)));
    ull d2  = f2x_fma(c3.x, apx, f2x_fma(c3.y, apy, f2x_mul(c4.x, apz)));
    ulonglong2 c5 = tp[5], c6 = tp[6], c7 = tp[7], c8 = tp[8];
    ull d3 = f2x_add(d1, c4.y);            // d1 - ab2
    ull d4 = f2x_add(d2, c5.x);            // d2 - abac
    ull d5 = f2x_add(d1, c5.x);            // d1 - abac
    ull d6 = f2x_add(d2, c5.y);            // d2 - ac2
    ull pb2 = f2x_fma(f2x_add(d1, d3), NEG1, pa2);
    ull pc2 = f2x_fma(f2x_add(d2, d6), NEG1, pa2);
    ull e = f2x_fma(d3, NEG1, d4);
    ull f = f2x_fma(d6, NEG1, d5);
    ull vAB = f2x_fma(f2x_mul(d1, d1), c6.x, pa2);
    ull vAC = f2x_fma(f2x_mul(d2, d2), c6.y, pa2);
    ull vBC = f2x_fma(f2x_mul(e, e), c7.x, pb2);
    ull vb = f2x_fma(f2x_mul(d1, d6), NEG1, f2x_mul(d5, d2));
    ull vc = f2x_fma(f2x_mul(d3, d2), NEG1, f2x_mul(d1, d4));
    ull va = f2x_fma(f2x_add(vb, vc), NEG1, c7.y);
    ull dI = f2x_fma(f2x_fma(vc, d2, f2x_mul(vb, d1)), c8.x, pa2);

    // lane 0
    {
        float m = fminf(f2lo(pa2), fminf(f2lo(pb2), f2lo(pc2)));
        if (f2lo(d1) > 0.0f && f2lo(d3) < 0.0f) m = fminf(m, f2lo(vAB));
        if (f2lo(d2) > 0.0f && f2lo(d6) < 0.0f) m = fminf(m, f2lo(vAC));
        if (f2lo(e) > 0.0f && f2lo(f) > 0.0f) m = fminf(m, f2lo(vBC));
        if (fminf(f2lo(va), fminf(f2lo(vb), f2lo(vc))) > 0.0f) m = fminf(m, f2lo(dI));
        m0 = fminf(m0, m);
    }
    // lane 1
    {
        float m = fminf(f2hi(pa2), fminf(f2hi(pb2), f2hi(pc2)));
        if (f2hi(d1) > 0.0f && f2hi(d3) < 0.0f) m = fminf(m, f2hi(vAB));
        if (f2hi(d2) > 0.0f && f2hi(d6) < 0.0f) m = fminf(m, f2hi(vAC));
        if (f2hi(e) > 0.0f && f2hi(f) > 0.0f) m = fminf(m, f2hi(vBC));
        if (fminf(f2hi(va), fminf(f2hi(vb), f2hi(vc))) > 0.0f) m = fminf(m, f2hi(dI));
        m1 = fminf(m1, m);
    }
}

// Kernel 3: brute-force min over triangles, packed f32x2, smem-staged tris.
// 2048 blocks (64 chunks x 8 point-groups x 4 batches) — ~8% wave tail vs
// ~45% at 1024 blocks with 740 resident.
__global__ void __launch_bounds__(TPB) dist_kernel(const float* __restrict__ pc) {
    __shared__ float4 sT[TILE * F4_PER_TRI];
    int b = blockIdx.z;
    int tid = threadIdx.x;
    const float* P = pc + (size_t)b * NP * 3;
    int ibase = blockIdx.y * (PPT * TPB) + tid;

    float px[PPT], py[PPT], pz[PPT];
#pragma unroll
    for (int k = 0; k < PPT; k++) {
        int i = ibase + k * TPB;
        px[k] = P[i * 3 + 0];
        py[k] = P[i * 3 + 1];
        pz[k] = P[i * 3 + 2];
    }
    ull px2[2], py2[2], pz2[2];
#pragma unroll
    for (int j = 0; j < 2; j++) {
        px2[j] = f2x(px[2 * j], px[2 * j + 1]);
        py2[j] = f2x(py[2 * j], py[2 * j + 1]);
        pz2[j] = f2x(pz[2 * j], pz[2 * j + 1]);
    }
    const ull NEG1 = f2x(-1.0f, -1.0f);
    float dm[PPT];
#pragma unroll
    for (int k = 0; k < PPT; k++) dm[k] = BIGF;

    const float4* src = g_tri2 + ((size_t)b * NT + (size_t)blockIdx.x * CHUNK_TRIS) * F4_PER_TRI;
#pragma unroll
    for (int i = 0; i < F4_PER_TRI; i++)
        sT[tid + i * TPB] = src[tid + i * TPB];
    __syncthreads();
#pragma unroll 2
    for (int t = 0; t < TILE; t++) {
        const ulonglong2* tp = reinterpret_cast<const ulonglong2*>(sT + t * F4_PER_TRI);
        tri_pair(tp, px2[0], py2[0], pz2[0], NEG1, dm[0], dm[1]);
        tri_pair(tp, px2[1], py2[1], pz2[1], NEG1, dm[2], dm[3]);
    }
#pragma unroll
    for (int k = 0; k < PPT; k++)
        atomicMin(&g_dmin[b * NP + ibase + k * TPB], __float_as_uint(dm[k]));
}

// Kernel 4a: parallel partial reduce. 32 blocks (8 slices x 4 batches) x 512 thr.
__global__ void reduceA_kernel(const float* __restrict__ pc) {
    __shared__ float sd[512];
    __shared__ float sc[512];
    int tid = threadIdx.x;
    int blk = blockIdx.x;
    int b = blk >> 3;
    int slice = blk & 7;
    int i = slice * 512 + tid;
    const float* p = pc + ((size_t)b * NP + i) * 3;
    float x = p[0], y = p[1], z = p[2];
    float m = (x != 0.0f || y != 0.0f || z != 0.0f) ? 1.0f : 0.0f;
    sd[tid] = __uint_as_float(g_dmin[b * NP + i]) * m;
    sc[tid] = m;
    __syncthreads();
    for (int s = 256; s > 0; s >>= 1) {
        if (tid < s) {
            sd[tid] += sd[tid + s];
            sc[tid] += sc[tid + s];
        }
        __syncthreads();
    }
    if (tid == 0) {
        g_psum[blk] = sd[0];
        g_pcnt[blk] = sc[0];
    }
}

// Kernel 4b: deterministic fixed-order final combine.
__global__ void reduceB_kernel(float* __restrict__ out) {
    if (threadIdx.x == 0) {
        float acc = 0.0f;
        for (int b = 0; b < NB; b++) {
            float s = 0.0f, c = 0.0f;
#pragma unroll
            for (int j = 0; j < 8; j++) {
                s += g_psum[b * 8 + j];
                c += g_pcnt[b * 8 + j];
            }
            acc += s / fmaxf(c, 1.0f);
        }
        out[0] = acc * (1.0f / NB);
    }
}

extern "C" void kernel_launch(void* const* d_in, const int* in_sizes, int n_in,
                              void* d_out, int out_size) {
    const float* vertices = (const float*)d_in[0];
    const float* pc = (const float*)d_in[1];
    const int* faces = (const int*)d_in[2];
    float* out = (float*)d_out;

    prep_kernel<<<(NB * 3 * NV + 255) / 256, 256>>>(vertices);
    tri_kernel<<<(NB * NT + 255) / 256, 256>>>(faces);
    dist_kernel<<<dim3(CHUNKS, NP / (PPT * TPB), NB), TPB>>>(pc);
    reduceA_kernel<<<32, 512>>>(pc);
    reduceB_kernel<<<1, 32>>>(out);
}

// round 14
// speedup vs baseline: 2.5253x; 1.0346x over previous
#include <cuda_runtime.h>

#define NB 4
#define NV 4096
#define NT 8192
#define NP 4096
#define EPSF 1e-12f
#define BIGF 3.402823466e38f

#define TPB 128
#define PPT 4              // points per thread (2 packed f32x2 streams)
#define CHUNKS_X 95        // 95*8*4 = 3040 blocks = 4x760 = 5x608 (exact waves)
#define MAX_CNT 87         // ceil(8192/95)
#define F4_PER_TRI 9       // 144 bytes per triangle, constants pre-duplicated

typedef unsigned long long ull;

static __device__ float g_pos[NB * NV * 3];
static __device__ float4 g_tri2[NB * NT * F4_PER_TRI];
static __device__ unsigned int g_dmin[NB * NP];
static __device__ float g_psum[32];
static __device__ float g_pcnt[32];

// ---------- packed f32x2 helpers (SASS FADD2/FMUL2/FFMA2) ----------
__device__ __forceinline__ ull f2x(float lo, float hi) {
    ull r; asm("mov.b64 %0, {%1, %2};" : "=l"(r) : "f"(lo), "f"(hi)); return r;
}
__device__ __forceinline__ ull f2x_add(ull a, ull b) {
    ull r; asm("add.rn.f32x2 %0, %1, %2;" : "=l"(r) : "l"(a), "l"(b)); return r;
}
__device__ __forceinline__ ull f2x_mul(ull a, ull b) {
    ull r; asm("mul.rn.f32x2 %0, %1, %2;" : "=l"(r) : "l"(a), "l"(b)); return r;
}
__device__ __forceinline__ ull f2x_fma(ull a, ull b, ull c) {
    ull r; asm("fma.rn.f32x2 %0, %1, %2, %3;" : "=l"(r) : "l"(a), "l"(b), "l"(c)); return r;
}
__device__ __forceinline__ float f2lo(ull v) { return __uint_as_float((unsigned)v); }
__device__ __forceinline__ float f2hi(ull v) { return __uint_as_float((unsigned)(v >> 32)); }

__device__ __forceinline__ float safe_inv(float x) {
    return (fabsf(x) < EPSF) ? 1.0f : (1.0f / x);
}

// Kernel 1: sigmoid + layout transpose (B,3,4096)->(B,4096,3), and init dmin.
__global__ void prep_kernel(const float* __restrict__ vertices) {
    int idx = blockIdx.x * blockDim.x + threadIdx.x;
    if (idx < NB * 3 * NV) {
        int b = idx / (3 * NV);
        int r = idx - b * 3 * NV;
        int d = r / NV;
        int w = r - d * NV;
        float v = vertices[idx];
        float s = 1.0f / (1.0f + expf(-v));
        g_pos[(b * NV + w) * 3 + d] = s;
    }
    if (idx < NB * NP) g_dmin[idx] = 0x7F7FFFFFu;  // +FLT_MAX bits
}

// Kernel 2: per-triangle precompute, constants duplicated into f32x2 pairs.
// Pair map: c0:(-ax,-ay) c1:(-az,abx) c2:(aby,abz) c3:(acx,acy) c4:(acz,-ab2)
//           c5:(-abac,-ac2) c6:(-iab2,-iac2) c7:(-ibc2,den) c8:(-iden,0)
__global__ void tri_kernel(const int* __restrict__ faces) {
    int idx = blockIdx.x * blockDim.x + threadIdx.x;
    if (idx >= NB * NT) return;
    int b = idx >> 13;
    int t = idx & (NT - 1);
    int i0 = faces[t * 3 + 0], i1 = faces[t * 3 + 1], i2 = faces[t * 3 + 2];
    const float* base = g_pos + b * NV * 3;
    float ax = base[i0 * 3 + 0], ay = base[i0 * 3 + 1], az = base[i0 * 3 + 2];
    float bx = base[i1 * 3 + 0], by = base[i1 * 3 + 1], bz = base[i1 * 3 + 2];
    float cx = base[i2 * 3 + 0], cy = base[i2 * 3 + 1], cz = base[i2 * 3 + 2];
    float abx = bx - ax, aby = by - ay, abz = bz - az;
    float acx = cx - ax, acy = cy - ay, acz = cz - az;
    float bcx = cx - bx, bcy = cy - by, bcz = cz - bz;
    float ab2  = abx * abx + aby * aby + abz * abz;
    float ac2  = acx * acx + acy * acy + acz * acz;
    float abac = abx * acx + aby * acy + abz * acz;
    float bc2  = bcx * bcx + bcy * bcy + bcz * bcz;
    float den  = ab2 * ac2 - abac * abac;   // == va+vb+vc
    float4* o = g_tri2 + (size_t)idx * F4_PER_TRI;
    o[0] = make_float4(-ax, -ax, -ay, -ay);
    o[1] = make_float4(-az, -az, abx, abx);
    o[2] = make_float4(aby, aby, abz, abz);
    o[3] = make_float4(acx, acx, acy, acy);
    o[4] = make_float4(acz, acz, -ab2, -ab2);
    o[5] = make_float4(-abac, -abac, -ac2, -ac2);
    o[6] = make_float4(-safe_inv(ab2), -safe_inv(ab2), -safe_inv(ac2), -safe_inv(ac2));
    o[7] = make_float4(-safe_inv(bc2), -safe_inv(bc2), den, den);
    o[8] = make_float4(-safe_inv(den), -safe_inv(den), 0.0f, 0.0f);
}

// Min-of-features closest distance, one triangle vs two packed points.
// m = min(pa2, pb2, pc2,
//         lineAB if 0<d1<ab2, lineAC if 0<d2<ac2 (d6<0), lineBC if e>0 && f>0,
//         face   if va,vb,vc > 0)
// Line dists: pa2 - d1^2/ab2 etc. Face: pa2 - (vb*d1 + vc*d2)/den (normal eqs).
__device__ __forceinline__ void tri_pair(const ulonglong2* __restrict__ tp,
                                         ull px, ull py, ull pz, ull NEG1,
                                         float& m0, float& m1)
{
    ulonglong2 c0 = tp[0], c1 = tp[1], c2 = tp[2], c3 = tp[3], c4 = tp[4];
    ull apx = f2x_add(px, c0.x);
    ull apy = f2x_add(py, c0.y);
    ull apz = f2x_add(pz, c1.x);
    ull pa2 = f2x_fma(apx, apx, f2x_fma(apy, apy, f2x_mul(apz, apz)));
    ull d1  = f2x_fma(c1.y, apx, f2x_fma(c2.x, apy, f2x_mul(c2.y, apz)));
    ull d2  = f2x_fma(c3.x, apx, f2x_fma(c3.y, apy, f2x_mul(c4.x, apz)));
    ulonglong2 c5 = tp[5], c6 = tp[6], c7 = tp[7], c8 = tp[8];
    ull d3 = f2x_add(d1, c4.y);            // d1 - ab2
    ull d4 = f2x_add(d2, c5.x);            // d2 - abac
    ull d5 = f2x_add(d1, c5.x);            // d1 - abac
    ull d6 = f2x_add(d2, c5.y);            // d2 - ac2
    ull pb2 = f2x_fma(f2x_add(d1, d3), NEG1, pa2);
    ull pc2 = f2x_fma(f2x_add(d2, d6), NEG1, pa2);
    ull e = f2x_fma(d3, NEG1, d4);
    ull f = f2x_fma(d6, NEG1, d5);
    ull vAB = f2x_fma(f2x_mul(d1, d1), c6.x, pa2);
    ull vAC = f2x_fma(f2x_mul(d2, d2), c6.y, pa2);
    ull vBC = f2x_fma(f2x_mul(e, e), c7.x, pb2);
    ull vb = f2x_fma(f2x_mul(d1, d6), NEG1, f2x_mul(d5, d2));
    ull vc = f2x_fma(f2x_mul(d3, d2), NEG1, f2x_mul(d1, d4));
    ull va = f2x_fma(f2x_add(vb, vc), NEG1, c7.y);
    ull dI = f2x_fma(f2x_fma(vc, d2, f2x_mul(vb, d1)), c8.x, pa2);

    // lane 0
    {
        float m = fminf(f2lo(pa2), fminf(f2lo(pb2), f2lo(pc2)));
        if (f2lo(d1) > 0.0f && f2lo(d3) < 0.0f) m = fminf(m, f2lo(vAB));
        if (f2lo(d2) > 0.0f && f2lo(d6) < 0.0f) m = fminf(m, f2lo(vAC));
        if (f2lo(e) > 0.0f && f2lo(f) > 0.0f) m = fminf(m, f2lo(vBC));
        if (fminf(f2lo(va), fminf(f2lo(vb), f2lo(vc))) > 0.0f) m = fminf(m, f2lo(dI));
        m0 = fminf(m0, m);
    }
    // lane 1
    {
        float m = fminf(f2hi(pa2), fminf(f2hi(pb2), f2hi(pc2)));
        if (f2hi(d1) > 0.0f && f2hi(d3) < 0.0f) m = fminf(m, f2hi(vAB));
        if (f2hi(d2) > 0.0f && f2hi(d6) < 0.0f) m = fminf(m, f2hi(vAC));
        if (f2hi(e) > 0.0f && f2hi(f) > 0.0f) m = fminf(m, f2hi(vBC));
        if (fminf(f2hi(va), fminf(f2hi(vb), f2hi(vc))) > 0.0f) m = fminf(m, f2hi(dI));
        m1 = fminf(m1, m);
    }
}

// Kernel 3: brute-force min over triangles, packed f32x2, smem-staged tris.
// Grid 95x8x4 = 3040 blocks, variable 86-87 tri ranges. smem padded to ~39KB
// to pin residency at 5 blocks/SM (152 SMs -> 760 resident -> 4 exact waves;
// if regs force 4 blocks/SM -> 608 resident -> 5 exact waves). No idle tail.
__global__ void __launch_bounds__(TPB) dist_kernel(const float* __restrict__ pc) {
    __shared__ float4 sT[MAX_CNT * F4_PER_TRI];
    __shared__ char s_pad[26496];          // occupancy pin: total smem > 228KB/6
    int b = blockIdx.z;
    int tid = threadIdx.x;
    if (tid > 100000) ((volatile char*)s_pad)[0] = 1;   // keep pad allocated
    const float* P = pc + (size_t)b * NP * 3;
    int ibase = blockIdx.y * (PPT * TPB) + tid;

    float px[PPT], py[PPT], pz[PPT];
#pragma unroll
    for (int k = 0; k < PPT; k++) {
        int i = ibase + k * TPB;
        px[k] = P[i * 3 + 0];
        py[k] = P[i * 3 + 1];
        pz[k] = P[i * 3 + 2];
    }
    ull px2[2], py2[2], pz2[2];
#pragma unroll
    for (int j = 0; j < 2; j++) {
        px2[j] = f2x(px[2 * j], px[2 * j + 1]);
        py2[j] = f2x(py[2 * j], py[2 * j + 1]);
        pz2[j] = f2x(pz[2 * j], pz[2 * j + 1]);
    }
    const ull NEG1 = f2x(-1.0f, -1.0f);
    float dm[PPT];
#pragma unroll
    for (int k = 0; k < PPT; k++) dm[k] = BIGF;

    int x = blockIdx.x;
    int tstart = (x * NT) / CHUNKS_X;
    int tend = ((x + 1) * NT) / CHUNKS_X;
    int cnt = tend - tstart;               // 86 or 87

    const float4* src = g_tri2 + ((size_t)b * NT + tstart) * F4_PER_TRI;
    for (int i = tid; i < cnt * F4_PER_TRI; i += TPB)
        sT[i] = src[i];
    __syncthreads();
#pragma unroll 2
    for (int t = 0; t < cnt; t++) {
        const ulonglong2* tp = reinterpret_cast<const ulonglong2*>(sT + t * F4_PER_TRI);
        tri_pair(tp, px2[0], py2[0], pz2[0], NEG1, dm[0], dm[1]);
        tri_pair(tp, px2[1], py2[1], pz2[1], NEG1, dm[2], dm[3]);
    }
#pragma unroll
    for (int k = 0; k < PPT; k++)
        atomicMin(&g_dmin[b * NP + ibase + k * TPB], __float_as_uint(dm[k]));
}

// Kernel 4a: parallel partial reduce. 32 blocks (8 slices x 4 batches) x 512 thr.
__global__ void reduceA_kernel(const float* __restrict__ pc) {
    __shared__ float sd[512];
    __shared__ float sc[512];
    int tid = threadIdx.x;
    int blk = blockIdx.x;
    int b = blk >> 3;
    int slice = blk & 7;
    int i = slice * 512 + tid;
    const float* p = pc + ((size_t)b * NP + i) * 3;
    float x = p[0], y = p[1], z = p[2];
    float m = (x != 0.0f || y != 0.0f || z != 0.0f) ? 1.0f : 0.0f;
    sd[tid] = __uint_as_float(g_dmin[b * NP + i]) * m;
    sc[tid] = m;
    __syncthreads();
    for (int s = 256; s > 0; s >>= 1) {
        if (tid < s) {
            sd[tid] += sd[tid + s];
            sc[tid] += sc[tid + s];
        }
        __syncthreads();
    }
    if (tid == 0) {
        g_psum[blk] = sd[0];
        g_pcnt[blk] = sc[0];
    }
}

// Kernel 4b: deterministic fixed-order final combine.
__global__ void reduceB_kernel(float* __restrict__ out) {
    if (threadIdx.x == 0) {
        float acc = 0.0f;
        for (int b = 0; b < NB; b++) {
            float s = 0.0f, c = 0.0f;
#pragma unroll
            for (int j = 0; j < 8; j++) {
                s += g_psum[b * 8 + j];
                c += g_pcnt[b * 8 + j];
            }
            acc += s / fmaxf(c, 1.0f);
        }
        out[0] = acc * (1.0f / NB);
    }
}

extern "C" void kernel_launch(void* const* d_in, const int* in_sizes, int n_in,
                              void* d_out, int out_size) {
    const float* vertices = (const float*)d_in[0];
    const float* pc = (const float*)d_in[1];
    const int* faces = (const int*)d_in[2];
    float* out = (float*)d_out;

    prep_kernel<<<(NB * 3 * NV + 255) / 256, 256>>>(vertices);
    tri_kernel<<<(NB * NT + 255) / 256, 256>>>(faces);
    dist_kernel<<<dim3(CHUNKS_X, NP / (PPT * TPB), NB), TPB>>>(pc);
    reduceA_kernel<<<32, 512>>>(pc);
    reduceB_kernel<<<1, 32>>>(out);
}